// round 15
// baseline (speedup 1.0000x reference)
#include <cuda_runtime.h>
#include <cuda_fp16.h>
#include <math.h>
#include <stdint.h>

// ---------------------------------------------------------------------------
// Problem constants
// ---------------------------------------------------------------------------
constexpr int BATCH = 256;
constexpr int N0 = 2048;
constexpr int N1 = 4096;
constexpr int N2 = 8192;
constexpr float LAMB = 0.5f;
constexpr int MAX_ITERS = 64;
constexpr float INV4096 = 1.0f / 4096.0f;

// ---------------------------------------------------------------------------
// Persistent state + scratch (__device__ globals).
// RULE (learned R3/R4/R9): device globals may ONLY be referenced from device
// code — never passed as kernel arguments from host.
// ---------------------------------------------------------------------------
__device__ float g_v0[BATCH * N0], g_t0[BATCH * N0], g_e0[BATCH * N0];
__device__ float g_v1[BATCH * N1], g_t1[BATCH * N1], g_e1[BATCH * N1];
__device__ float sP0[4][BATCH * N0];   // e1@W0 partials (UPD0, 4 K-parts)
__device__ float sP1[8][BATCH * N1];   // e2@W1 partials (UPD1, 8 K-parts)
__device__ float sQ1[2][BATCH * N1];   // t0@W0^T partials (2 parts)
__device__ float sQ2[4][BATCH * N2];   // t1@W1^T partials (4 parts)
// fp16-split packed activations (hi, lo*4096), 2 fp16 per u32, pairs along k
__device__ uint2 g_t0ph[BATCH * N0 / 4], g_t0pl[BATCH * N0 / 4];
__device__ uint2 g_t1ph[BATCH * N1 / 4], g_t1pl[BATCH * N1 / 4];
__device__ uint2 g_e1ph[BATCH * N1 / 4], g_e1pl[BATCH * N1 / 4];
__device__ uint2 g_e2ph[BATCH * N2 / 4], g_e2pl[BATCH * N2 / 4];
// fp16-split packed weights. ALL stored [n][kpair] (n-major, BT layout):
//   bt*: natural rows (B = W, k along W's row)       — modes 0,1
//   tr*: transposed   (B = W^T, k along W's column)  — modes 2,3
__device__ uint32_t g_W0bth[(size_t)N1 * N0 / 2], g_W0btl[(size_t)N1 * N0 / 2];
__device__ uint32_t g_W0trh[(size_t)N1 * N0 / 2], g_W0trl[(size_t)N1 * N0 / 2];
__device__ uint32_t g_W1bth[(size_t)N2 * N1 / 2], g_W1btl[(size_t)N2 * N1 / 2];
__device__ uint32_t g_W1trh[(size_t)N2 * N1 / 2], g_W1trl[(size_t)N2 * N1 / 2];
__device__ double g_loss[MAX_ITERS];

// ---------------------------------------------------------------------------
// PTX helpers (sm_80 baseline; ptxas target is plain sm_103)
// ---------------------------------------------------------------------------
__device__ __forceinline__ uint32_t s2u(const void* p) {
    uint32_t a;
    asm("{ .reg .u64 t; cvta.to.shared.u64 t, %1; cvt.u32.u64 %0, t; }"
        : "=r"(a) : "l"(p));
    return a;
}
__device__ __forceinline__ void cp_async16(uint32_t saddr, const void* gaddr) {
    asm volatile("cp.async.cg.shared.global [%0], [%1], 16;"
                 :: "r"(saddr), "l"(gaddr) : "memory");
}
__device__ __forceinline__ void cp_commit() {
    asm volatile("cp.async.commit_group;" ::: "memory");
}
template <int N>
__device__ __forceinline__ void cp_wait() {
    asm volatile("cp.async.wait_group %0;" :: "n"(N) : "memory");
}
__device__ __forceinline__ void mma16(float* d, const uint32_t* a, const uint32_t* b) {
    asm volatile(
        "mma.sync.aligned.m16n8k16.row.col.f32.f16.f16.f32 "
        "{%0,%1,%2,%3}, {%4,%5,%6,%7}, {%8,%9}, {%0,%1,%2,%3};"
        : "+f"(d[0]), "+f"(d[1]), "+f"(d[2]), "+f"(d[3])
        : "r"(a[0]), "r"(a[1]), "r"(a[2]), "r"(a[3]), "r"(b[0]), "r"(b[1]));
}
__device__ __forceinline__ void ldsm4(uint32_t* r, uint32_t addr) {
    asm volatile("ldmatrix.sync.aligned.m8n8.x4.shared.b16 {%0,%1,%2,%3}, [%4];"
                 : "=r"(r[0]), "=r"(r[1]), "=r"(r[2]), "=r"(r[3]) : "r"(addr));
}

__device__ __forceinline__ uint32_t packh2(__half a, __half b) {
    return (uint32_t)__half_as_ushort(a) | ((uint32_t)__half_as_ushort(b) << 16);
}
__device__ __forceinline__ void split4(float4 x, uint2& hi, uint2& lo) {
    __half h0 = __float2half_rn(x.x), h1 = __float2half_rn(x.y);
    __half h2 = __float2half_rn(x.z), h3 = __float2half_rn(x.w);
    hi.x = packh2(h0, h1);
    hi.y = packh2(h2, h3);
    float l0 = (x.x - __half2float(h0)) * 4096.f;
    float l1 = (x.y - __half2float(h1)) * 4096.f;
    float l2 = (x.z - __half2float(h2)) * 4096.f;
    float l3 = (x.w - __half2float(h3)) * 4096.f;
    lo.x = packh2(__float2half_rn(l0), __float2half_rn(l1));
    lo.y = packh2(__float2half_rn(l2), __float2half_rn(l3));
}

// ---------------------------------------------------------------------------
// prep: weight splits. All outputs [n][kpair] n-major.
// split_w_bt: pairs along W's row (natural).
// split_w_tr: pairs along W's column (transposed pack) via tiled transpose.
// ---------------------------------------------------------------------------
__global__ void split_w_bt(const float* __restrict__ W, int which, int npairs) {
    uint32_t* __restrict__ hi = which ? g_W1bth : g_W0bth;
    uint32_t* __restrict__ lo = which ? g_W1btl : g_W0btl;
    int i0 = blockIdx.x * blockDim.x + threadIdx.x;
    int stride = gridDim.x * blockDim.x;
    for (int i = i0; i < npairs; i += stride) {
        float w0 = W[2 * i], w1 = W[2 * i + 1];
        __half h0 = __float2half_rn(w0), h1 = __float2half_rn(w1);
        hi[i] = packh2(h0, h1);
        lo[i] = packh2(__float2half_rn((w0 - __half2float(h0)) * 4096.f),
                       __float2half_rn((w1 - __half2float(h1)) * 4096.f));
    }
}
// W[R][C] -> O[C][R/2]: O[n][kp] = pack(W[2kp][n], W[2kp+1][n])
__global__ void split_w_tr(const float* __restrict__ W, int which) {
    uint32_t* __restrict__ hi = which ? g_W1trh : g_W0trh;
    uint32_t* __restrict__ lo = which ? g_W1trl : g_W0trl;
    const int R = which ? N2 : N1;
    const int C = which ? N1 : N0;
    const int KPF = R / 2;
    __shared__ float t0[32][33], t1[32][33];
    int n0 = blockIdx.x * 32;
    int kp0 = blockIdx.y * 32;
    int x = threadIdx.x, y = threadIdx.y;  // block (32, 8)
#pragma unroll
    for (int dy = 0; dy < 32; dy += 8) {
        int kp = y + dy;
        t0[kp][x] = W[(size_t)(2 * (kp0 + kp)) * C + n0 + x];
        t1[kp][x] = W[(size_t)(2 * (kp0 + kp) + 1) * C + n0 + x];
    }
    __syncthreads();
#pragma unroll
    for (int dy = 0; dy < 32; dy += 8) {
        int n = y + dy;
        float w0 = t0[x][n], w1 = t1[x][n];
        __half h0 = __float2half_rn(w0), h1 = __float2half_rn(w1);
        size_t o = (size_t)(n0 + n) * KPF + kp0 + x;
        hi[o] = packh2(h0, h1);
        lo[o] = packh2(__float2half_rn((w0 - __half2float(h0)) * 4096.f),
                       __float2half_rn((w1 - __half2float(h1)) * 4096.f));
    }
}

// ---------------------------------------------------------------------------
// init
// ---------------------------------------------------------------------------
__global__ void init_state_k(const float* __restrict__ memory) {
    int i0 = blockIdx.x * blockDim.x + threadIdx.x;
    int stride = gridDim.x * blockDim.x;
    if (i0 < MAX_ITERS) g_loss[i0] = 0.0;
    for (int i = i0; i < BATCH * N0 / 4; i += stride) {
        float4 m4 = *(const float4*)&memory[(i * 4) & (N0 - 1)];
        ((float4*)g_v0)[i] = m4;
        float4 t4 = make_float4(tanhf(m4.x), tanhf(m4.y), tanhf(m4.z), tanhf(m4.w));
        ((float4*)g_t0)[i] = t4;
        uint2 hi, lo;
        split4(t4, hi, lo);
        g_t0ph[i] = hi;
        g_t0pl[i] = lo;
        ((float4*)g_e0)[i] = make_float4(0.f, 0.f, 0.f, 0.f);
    }
    for (int i = i0; i < BATCH * N1 / 4; i += stride) {
        ((float4*)g_e1)[i] = make_float4(0.f, 0.f, 0.f, 0.f);
        g_e1ph[i] = make_uint2(0, 0);
        g_e1pl[i] = make_uint2(0, 0);
    }
}

// ---------------------------------------------------------------------------
// Split-K GEMM (pure partial writer), fp16-split emulation (~fp32 accurate).
// D = [Ah.Bh] + 2^-12 [Ah.Bl' + Al'.Bh].  Unified BT path: all B operands
// stored [n][kpair].  Fragments via ldmatrix.x4 (12 LDSM + 48 HMMA per
// k16-step per warp).  CTA 128m x 64n, 4 m-warps (each 32x64). KC=16,
// 4-stage cp.async, cp_wait<2>, KPART=1024, 3 CTAs/SM.
// Modes: 0: t0@W0^T -> sQ1[p] (2p)   1: t1@W1^T -> sQ2[p] (4p)
//        2: e1@W0   -> sP0[p] (4p)   3: e2@W1   -> sP1[p] (8p)
// ---------------------------------------------------------------------------
constexpr int KC = 16, KP = 8, KPART = 1024;
constexpr int BMT = 128;
constexpr int LDW = 12;   // smem row stride (u32 words): 8 data + 4 pad
constexpr int TILEW_A = BMT * LDW;    // 1536 words per A component
constexpr int TILEW_B = 64 * LDW;     // 768 words per B component
constexpr int STAGE_W = 2 * TILEW_A + 2 * TILEW_B;  // 4608 words (18 KB)
constexpr int STG = 4;
constexpr int SMEM_BYTES = STG * STAGE_W * 4;       // 73728 B -> 3 CTAs/SM

template <int MODE>
__device__ __forceinline__ void gemm_body(int bx, int by, int part) {
    constexpr int NF = (MODE == 0) ? N1 : (MODE == 1) ? N2 : (MODE == 2) ? N0 : N1;
    constexpr int KF = (MODE == 0) ? N0 : (MODE == 1) ? N1 : (MODE == 2) ? N1 : N2;
    constexpr int KPF = KF / 2;      // pairs per row (A and B share this)
    constexpr int NCH = KPART / KC;  // 64

    const uint32_t* __restrict__ Aph = (const uint32_t*)(
        (MODE == 0) ? g_t0ph : (MODE == 1) ? g_t1ph : (MODE == 2) ? g_e1ph : g_e2ph);
    const uint32_t* __restrict__ Apl = (const uint32_t*)(
        (MODE == 0) ? g_t0pl : (MODE == 1) ? g_t1pl : (MODE == 2) ? g_e1pl : g_e2pl);
    const uint32_t* __restrict__ Bph =
        (MODE == 0) ? g_W0bth : (MODE == 1) ? g_W1bth : (MODE == 2) ? g_W0trh : g_W1trh;
    const uint32_t* __restrict__ Bpl =
        (MODE == 0) ? g_W0btl : (MODE == 1) ? g_W1btl : (MODE == 2) ? g_W0trl : g_W1trl;
    float* __restrict__ dst =
        (MODE == 0) ? sQ1[part] : (MODE == 1) ? sQ2[part]
        : (MODE == 2) ? sP0[part] : sP1[part];

    extern __shared__ uint32_t smw[];
    const uint32_t sb = s2u(smw);
    const int tid = threadIdx.x;
    const int wid = tid >> 5;   // 0..3 (m-warp)
    const int lane = tid & 31;
    const int tq = lane >> 2;   // 0..7
    const int tr = lane & 3;    // 0..3
    const int lr = lane & 15;          // ldmatrix row within 16
    const int lw = (lane >> 4) * 4;    // ldmatrix k-word offset (0 or 4)
    const int bm = by * BMT;
    const int bn = bx * 64;

    auto load_chunk = [&](int c, int st) {
        const int ktp = part * (KPART / 2) + c * KP;
        uint32_t base = sb + (uint32_t)st * STAGE_W * 4;
        // A: 128 rows x 8 pairs, hi+lo -> 256 16B-chunks per comp, 2/thread
#pragma unroll
        for (int i = 0; i < 2; i++) {
            int ch = tid + i * 128;
            int row = ch >> 1, cs = (ch & 1) * 4;
            size_t go = (size_t)(bm + row) * KPF + ktp + cs;
            uint32_t so = (row * LDW + cs) * 4;
            cp_async16(base + so, Aph + go);
            cp_async16(base + TILEW_A * 4 + so, Apl + go);
        }
        // B: 64 n-rows x 8 pairs -> 128 16B-chunks per comp, 1/thread
        uint32_t bbase = base + 2 * TILEW_A * 4;
        int row = tid >> 1, cs = (tid & 1) * 4;
        size_t go = (size_t)(bn + row) * KPF + ktp + cs;
        uint32_t so = (row * LDW + cs) * 4;
        cp_async16(bbase + so, Bph + go);
        cp_async16(bbase + TILEW_B * 4 + so, Bpl + go);
        cp_commit();
    };

    float d0[2][8][4], d1[2][8][4];
#pragma unroll
    for (int mi = 0; mi < 2; mi++)
#pragma unroll
        for (int ni = 0; ni < 8; ni++)
#pragma unroll
            for (int r = 0; r < 4; r++) { d0[mi][ni][r] = 0.0f; d1[mi][ni][r] = 0.0f; }

    load_chunk(0, 0);
    load_chunk(1, 1);
    load_chunk(2, 2);

    // per-lane ldmatrix offsets (within a component tile), in bytes
    const uint32_t aoff = (uint32_t)((wid * 32 + lr) * LDW + lw) * 4;
    const uint32_t boff = (uint32_t)(lr * LDW + lw) * 4;

    for (int c = 0; c < NCH; c++) {
        cp_wait<2>();
        __syncthreads();
        int nc = c + 3;
        if (nc < NCH) load_chunk(nc, nc & 3);
        else cp_commit();  // keep group accounting aligned through the tail

        uint32_t base = sb + (uint32_t)(c & 3) * STAGE_W * 4;
        uint32_t aH = base + aoff;
        uint32_t aL = aH + TILEW_A * 4;
        uint32_t bH = base + 2 * TILEW_A * 4 + boff;
        uint32_t bL = bH + TILEW_B * 4;

        // A fragments: regs {a0,a1,a2,a3} per mi (16m x 16k)
        uint32_t ah[2][4], al[2][4];
#pragma unroll
        for (int mi = 0; mi < 2; mi++) {
            ldsm4(ah[mi], aH + mi * (16 * LDW * 4));
            ldsm4(al[mi], aL + mi * (16 * LDW * 4));
        }
        // B fragments: per np (16n x 16k): regs {b0(2np), b0(2np+1), b1(2np), b1(2np+1)}
        uint32_t bh[4][4], bl[4][4];
#pragma unroll
        for (int np = 0; np < 4; np++) {
            ldsm4(bh[np], bH + np * (16 * LDW * 4));
            ldsm4(bl[np], bL + np * (16 * LDW * 4));
        }
#pragma unroll
        for (int mi = 0; mi < 2; mi++)
#pragma unroll
            for (int ni = 0; ni < 8; ni++) {
                const int np = ni >> 1, o = ni & 1;
                uint32_t bbh[2] = {bh[np][o], bh[np][2 + o]};
                uint32_t bbl[2] = {bl[np][o], bl[np][2 + o]};
                mma16(d0[mi][ni], ah[mi], bbh);   // hh
                mma16(d1[mi][ni], ah[mi], bbl);   // h * lo'
                mma16(d1[mi][ni], al[mi], bbh);   // lo' * h
            }
    }

    // write partial tile: D = d0 + d1 * 2^-12
#pragma unroll
    for (int mi = 0; mi < 2; mi++)
#pragma unroll
        for (int ni = 0; ni < 8; ni++)
#pragma unroll
            for (int hf = 0; hf < 2; hf++) {
                int row = bm + wid * 32 + mi * 16 + tq + hf * 8;
                int col = bn + ni * 8 + tr * 2;
                float px = d0[mi][ni][hf * 2] + d1[mi][ni][hf * 2] * INV4096;
                float py = d0[mi][ni][hf * 2 + 1] + d1[mi][ni][hf * 2 + 1] * INV4096;
                *(float2*)&dst[(size_t)row * NF + col] = make_float2(px, py);
            }
}

// ---------------------------------------------------------------------------
// Fused phase GEMM kernels (1-D grid of uniform-duration CTAs)
// upd: mode2 (4p x 32n x 2m = 256) + mode3 (8 x 64 x 2 = 1024) = 1280
// err: mode0 (2p x 64n x 2m = 256) + mode1 (4 x 128 x 2 = 1024) = 1280
// ---------------------------------------------------------------------------
__global__ __launch_bounds__(128, 3)
void upd_gemm() {
    int b = blockIdx.x;
    if (b < 256) {
        int part = b >> 6, t = b & 63;
        gemm_body<2>(t & 31, t >> 5, part);
    } else {
        int b2 = b - 256;
        int part = b2 >> 7, t = b2 & 127;
        gemm_body<3>(t & 63, t >> 6, part);
    }
}
__global__ __launch_bounds__(128, 3)
void err_gemm(int boff) {
    int b = blockIdx.x + boff;
    if (b < 256) {
        int part = b >> 7, t = b & 127;
        gemm_body<0>(t & 63, t >> 6, part);
    } else {
        int b2 = b - 256;
        int part = b2 >> 8, t = b2 & 255;
        gemm_body<1>(t & 127, t >> 7, part);
    }
}

// ---------------------------------------------------------------------------
// Epilogue kernels (elementwise, float4; also emit packed fp16 splits)
// ---------------------------------------------------------------------------
__device__ __forceinline__ void block_loss(float lsum, int loss_idx) {
    __shared__ float wred[8];
    int tid = threadIdx.x;
#pragma unroll
    for (int o = 16; o > 0; o >>= 1)
        lsum += __shfl_down_sync(0xffffffffu, lsum, o);
    if ((tid & 31) == 0) wred[tid >> 5] = lsum;
    __syncthreads();
    if (tid == 0 && loss_idx >= 0) {
        float s = 0.f;
#pragma unroll
        for (int w = 0; w < 8; w++) s += wred[w];
        atomicAdd(&g_loss[loss_idx], (double)s);
    }
}

// grid 1536 x 256 : v0 update (131072 f4) then v1 update (262144 f4)
__global__ __launch_bounds__(256)
void upd_epi(const float* __restrict__ memory, const float* __restrict__ lr_p,
             int loss_idx) {
    int i = blockIdx.x * blockDim.x + threadIdx.x;
    float lr = *lr_p;
    float lsum = 0.f;
    if (i < BATCH * N0 / 4) {
        float4 acc[4];
#pragma unroll
        for (int p = 0; p < 4; p++) acc[p] = ((const float4*)sP0[p])[i];
        float4 v4 = ((const float4*)g_v0)[i];
        float4 e4 = ((const float4*)g_e0)[i];
        float4 t4 = ((const float4*)g_t0)[i];
        float4 m4 = *(const float4*)&memory[(i * 4) & (N0 - 1)];
        float* v = &v4.x; float* e = &e4.x; float* t = &t4.x; float* m = &m4.x;
        float4 nv4, nt4, ne4;
        float* nv = &nv4.x; float* nt = &nt4.x; float* ne = &ne4.x;
#pragma unroll
        for (int c = 0; c < 4; c++) {
            float g = ((&acc[0].x)[c] + (&acc[1].x)[c]) +
                      ((&acc[2].x)[c] + (&acc[3].x)[c]);
            float sg = (v[c] > 0.f) ? 1.f : ((v[c] < 0.f) ? -1.f : 0.f);
            float x = fmaxf(v[c] + lr * (-e[c] - LAMB * sg + (1.f - t[c] * t[c]) * g), 0.f);
            nv[c] = x;
            nt[c] = tanhf(x);
            float er = x - m[c];
            ne[c] = er;
            lsum += er * er;
        }
        ((float4*)g_v0)[i] = nv4;
        ((float4*)g_t0)[i] = nt4;
        ((float4*)g_e0)[i] = ne4;
        uint2 hi, lo;
        split4(nt4, hi, lo);
        g_t0ph[i] = hi;
        g_t0pl[i] = lo;
    } else {
        int j = i - BATCH * N0 / 4;
        float4 acc[8];
#pragma unroll
        for (int p = 0; p < 8; p++) acc[p] = ((const float4*)sP1[p])[j];
        float4 v4 = ((const float4*)g_v1)[j];
        float4 e4 = ((const float4*)g_e1)[j];
        float4 t4 = ((const float4*)g_t1)[j];
        float* v = &v4.x; float* e = &e4.x; float* t = &t4.x;
        float4 nv4, nt4;
        float* nv = &nv4.x; float* nt = &nt4.x;
#pragma unroll
        for (int c = 0; c < 4; c++) {
            float g = (((&acc[0].x)[c] + (&acc[1].x)[c]) +
                       ((&acc[2].x)[c] + (&acc[3].x)[c])) +
                      (((&acc[4].x)[c] + (&acc[5].x)[c]) +
                       ((&acc[6].x)[c] + (&acc[7].x)[c]));
            float x = fmaxf(v[c] + lr * (-e[c] + (1.f - t[c] * t[c]) * g), 0.f);
            nv[c] = x;
            nt[c] = tanhf(x);
        }
        ((float4*)g_v1)[j] = nv4;
        ((float4*)g_t1)[j] = nt4;
        uint2 hi, lo;
        split4(nt4, hi, lo);
        g_t1ph[j] = hi;
        g_t1pl[j] = lo;
    }
    block_loss(lsum, loss_idx);
}

// grid 3072 x 256 : e1 (262144 f4, skipped when mode=1) then e2 (524288 f4)
__global__ __launch_bounds__(256)
void err_epi(const float* __restrict__ inp, int loss_idx, int mode) {
    int i = blockIdx.x * blockDim.x + threadIdx.x;
    float lsum = 0.f;
    if (i < BATCH * N1 / 4) {
        if (mode == 0) {
            float4 q0 = ((const float4*)sQ1[0])[i];
            float4 q1 = ((const float4*)sQ1[1])[i];
            float4 v = ((const float4*)g_v1)[i];
            float4 e = make_float4(v.x - (q0.x + q1.x), v.y - (q0.y + q1.y),
                                   v.z - (q0.z + q1.z), v.w - (q0.w + q1.w));
            ((float4*)g_e1)[i] = e;
            uint2 hi, lo;
            split4(e, hi, lo);
            g_e1ph[i] = hi;
            g_e1pl[i] = lo;
            lsum = e.x * e.x + e.y * e.y + e.z * e.z + e.w * e.w;
        }
    } else {
        int j = i - BATCH * N1 / 4;
        float4 q0 = ((const float4*)sQ2[0])[j];
        float4 q1 = ((const float4*)sQ2[1])[j];
        float4 q2 = ((const float4*)sQ2[2])[j];
        float4 q3 = ((const float4*)sQ2[3])[j];
        float4 x = ((const float4*)inp)[j];
        float4 e = make_float4(x.x - ((q0.x + q1.x) + (q2.x + q3.x)),
                               x.y - ((q0.y + q1.y) + (q2.y + q3.y)),
                               x.z - ((q0.z + q1.z) + (q2.z + q3.z)),
                               x.w - ((q0.w + q1.w) + (q2.w + q3.w)));
        uint2 hi, lo;
        split4(e, hi, lo);
        g_e2ph[j] = hi;
        g_e2pl[j] = lo;
        lsum = e.x * e.x + e.y * e.y + e.z * e.z + e.w * e.w;
    }
    block_loss(lsum, loss_idx);
}

// grid 1024 x 256 : v1 = sum(sQ1), t1 = tanh(v1) (+ t1 splits)
__global__ __launch_bounds__(256)
void fwd_epi() {
    int i = blockIdx.x * blockDim.x + threadIdx.x;
    float4 q0 = ((const float4*)sQ1[0])[i];
    float4 q1 = ((const float4*)sQ1[1])[i];
    float4 q = make_float4(q0.x + q1.x, q0.y + q1.y, q0.z + q1.z, q0.w + q1.w);
    ((float4*)g_v1)[i] = q;
    float4 t = make_float4(tanhf(q.x), tanhf(q.y), tanhf(q.z), tanhf(q.w));
    ((float4*)g_t1)[i] = t;
    uint2 hi, lo;
    split4(t, hi, lo);
    g_t1ph[i] = hi;
    g_t1pl[i] = lo;
}

__global__ void finalize_kernel(float* __restrict__ out, int n) {
    int i = threadIdx.x;
    if (i < n) out[i] = (float)(g_loss[i] * (100.0 / (double)BATCH));
}

// ---------------------------------------------------------------------------
// Launch (graph-capturable)
// Inputs: batch_inp, W0, W1, memory, n_iters, inf_lr
// ---------------------------------------------------------------------------
extern "C" void kernel_launch(void* const* d_in, const int* in_sizes, int n_in,
                              void* d_out, int out_size) {
    const float* batch_inp = (const float*)d_in[0];
    const float* W0 = (const float*)d_in[1];
    const float* W1 = (const float*)d_in[2];
    const float* memory = (const float*)d_in[3];
    const float* inf_lr = (const float*)d_in[5];

    int n_iters = out_size;
    if (n_iters > MAX_ITERS) n_iters = MAX_ITERS;

    cudaFuncSetAttribute(upd_gemm, cudaFuncAttributeMaxDynamicSharedMemorySize, SMEM_BYTES);
    cudaFuncSetAttribute(err_gemm, cudaFuncAttributeMaxDynamicSharedMemorySize, SMEM_BYTES);

    // weight splits (pure function of inputs; recomputed each call)
    split_w_bt<<<2048, 256>>>(W0, 0, N1 * N0 / 2);
    split_w_bt<<<4096, 256>>>(W1, 1, N2 * N1 / 2);
    split_w_tr<<<dim3(N0 / 32, N1 / 64), dim3(32, 8)>>>(W0, 0);
    split_w_tr<<<dim3(N1 / 32, N2 / 64), dim3(32, 8)>>>(W1, 1);
    init_state_k<<<512, 256>>>(memory);

    // init: v1 = t0@W0^T, t1 = tanh(v1); e1 stays exactly 0; e2 = inp - t1@W1^T
    err_gemm<<<256, 128, SMEM_BYTES>>>(0);      // mode 0 -> sQ1[0..1]
    fwd_epi<<<1024, 256>>>();
    err_gemm<<<1024, 128, SMEM_BYTES>>>(256);   // mode 1 -> sQ2[0..3]
    err_epi<<<3072, 256>>>(batch_inp, -1, 1);   // e2 only, no loss

    for (int it = 0; it < n_iters; it++) {
        upd_gemm<<<1280, 128, SMEM_BYTES>>>();
        upd_epi<<<1536, 256>>>(memory, inf_lr, it);
        err_gemm<<<1280, 128, SMEM_BYTES>>>(0);
        err_epi<<<3072, 256>>>(batch_inp, it, 0);
    }

    finalize_kernel<<<1, MAX_ITERS>>>((float*)d_out, n_iters);
}

// round 16
// speedup vs baseline: 1.1237x; 1.1237x over previous
#include <cuda_runtime.h>
#include <cuda_fp16.h>
#include <math.h>
#include <stdint.h>

// ---------------------------------------------------------------------------
// Problem constants
// ---------------------------------------------------------------------------
constexpr int BATCH = 256;
constexpr int N0 = 2048;
constexpr int N1 = 4096;
constexpr int N2 = 8192;
constexpr float LAMB = 0.5f;
constexpr int MAX_ITERS = 64;
constexpr float INV4096 = 1.0f / 4096.0f;

// ---------------------------------------------------------------------------
// Persistent state + scratch (__device__ globals).
// RULE (learned R3/R4/R9): device globals may ONLY be referenced from device
// code — never passed as kernel arguments from host.
// ---------------------------------------------------------------------------
__device__ float g_v0[BATCH * N0], g_t0[BATCH * N0], g_e0[BATCH * N0];
__device__ float g_v1[BATCH * N1], g_t1[BATCH * N1], g_e1[BATCH * N1];
__device__ float sP0[4][BATCH * N0];   // e1@W0 partials (UPD0, 4 K-parts)
__device__ float sP1[8][BATCH * N1];   // e2@W1 partials (UPD1, 8 K-parts)
__device__ float sQ1[2][BATCH * N1];   // t0@W0^T partials (2 parts)
__device__ float sQ2[4][BATCH * N2];   // t1@W1^T partials (4 parts)
// fp16-split packed activations (hi, lo*4096), 2 fp16 per u32, pairs along k
__device__ uint2 g_t0ph[BATCH * N0 / 4], g_t0pl[BATCH * N0 / 4];
__device__ uint2 g_t1ph[BATCH * N1 / 4], g_t1pl[BATCH * N1 / 4];
__device__ uint2 g_e1ph[BATCH * N1 / 4], g_e1pl[BATCH * N1 / 4];
__device__ uint2 g_e2ph[BATCH * N2 / 4], g_e2pl[BATCH * N2 / 4];
// fp16-split packed weights, both orientations
__device__ uint32_t g_W0bth[(size_t)N1 * N0 / 2], g_W0btl[(size_t)N1 * N0 / 2];
__device__ uint32_t g_W0nnh[(size_t)N1 * N0 / 2], g_W0nnl[(size_t)N1 * N0 / 2];
__device__ uint32_t g_W1bth[(size_t)N2 * N1 / 2], g_W1btl[(size_t)N2 * N1 / 2];
__device__ uint32_t g_W1nnh[(size_t)N2 * N1 / 2], g_W1nnl[(size_t)N2 * N1 / 2];
__device__ double g_loss[MAX_ITERS];

// ---------------------------------------------------------------------------
// PTX helpers (sm_80 baseline; ptxas target is plain sm_103)
// ---------------------------------------------------------------------------
__device__ __forceinline__ uint32_t s2u(const void* p) {
    uint32_t a;
    asm("{ .reg .u64 t; cvta.to.shared.u64 t, %1; cvt.u32.u64 %0, t; }"
        : "=r"(a) : "l"(p));
    return a;
}
__device__ __forceinline__ void cp_async16(uint32_t saddr, const void* gaddr) {
    asm volatile("cp.async.cg.shared.global [%0], [%1], 16;"
                 :: "r"(saddr), "l"(gaddr) : "memory");
}
__device__ __forceinline__ void cp_commit() {
    asm volatile("cp.async.commit_group;" ::: "memory");
}
template <int N>
__device__ __forceinline__ void cp_wait() {
    asm volatile("cp.async.wait_group %0;" :: "n"(N) : "memory");
}
__device__ __forceinline__ void mma16(float* d, const uint32_t* a, const uint32_t* b) {
    asm volatile(
        "mma.sync.aligned.m16n8k16.row.col.f32.f16.f16.f32 "
        "{%0,%1,%2,%3}, {%4,%5,%6,%7}, {%8,%9}, {%0,%1,%2,%3};"
        : "+f"(d[0]), "+f"(d[1]), "+f"(d[2]), "+f"(d[3])
        : "r"(a[0]), "r"(a[1]), "r"(a[2]), "r"(a[3]), "r"(b[0]), "r"(b[1]));
}

__device__ __forceinline__ uint32_t packh2(__half a, __half b) {
    return (uint32_t)__half_as_ushort(a) | ((uint32_t)__half_as_ushort(b) << 16);
}
__device__ __forceinline__ void split4(float4 x, uint2& hi, uint2& lo) {
    __half h0 = __float2half_rn(x.x), h1 = __float2half_rn(x.y);
    __half h2 = __float2half_rn(x.z), h3 = __float2half_rn(x.w);
    hi.x = packh2(h0, h1);
    hi.y = packh2(h2, h3);
    float l0 = (x.x - __half2float(h0)) * 4096.f;
    float l1 = (x.y - __half2float(h1)) * 4096.f;
    float l2 = (x.z - __half2float(h2)) * 4096.f;
    float l3 = (x.w - __half2float(h3)) * 4096.f;
    lo.x = packh2(__float2half_rn(l0), __float2half_rn(l1));
    lo.y = packh2(__float2half_rn(l2), __float2half_rn(l3));
}

// ---------------------------------------------------------------------------
// prep: weight splits (device-side symbol selection per RULE)
// ---------------------------------------------------------------------------
__global__ void split_w_bt(const float* __restrict__ W, int which, int npairs) {
    uint32_t* __restrict__ hi = which ? g_W1bth : g_W0bth;
    uint32_t* __restrict__ lo = which ? g_W1btl : g_W0btl;
    int i0 = blockIdx.x * blockDim.x + threadIdx.x;
    int stride = gridDim.x * blockDim.x;
    for (int i = i0; i < npairs; i += stride) {
        float w0 = W[2 * i], w1 = W[2 * i + 1];
        __half h0 = __float2half_rn(w0), h1 = __float2half_rn(w1);
        hi[i] = packh2(h0, h1);
        lo[i] = packh2(__float2half_rn((w0 - __half2float(h0)) * 4096.f),
                       __float2half_rn((w1 - __half2float(h1)) * 4096.f));
    }
}
__global__ void split_w_nn(const float* __restrict__ W, int which) {
    uint32_t* __restrict__ hi = which ? g_W1nnh : g_W0nnh;
    uint32_t* __restrict__ lo = which ? g_W1nnl : g_W0nnl;
    const int N = which ? N1 : N0;
    const int npairs_total = which ? (N2 / 2) * N1 : (N1 / 2) * N0;
    int i0 = blockIdx.x * blockDim.x + threadIdx.x;
    int stride = gridDim.x * blockDim.x;
    for (int i = i0; i < npairs_total; i += stride) {
        int kp = i / N, n = i - kp * N;
        float w0 = W[(size_t)(2 * kp) * N + n];
        float w1 = W[(size_t)(2 * kp + 1) * N + n];
        __half h0 = __float2half_rn(w0), h1 = __float2half_rn(w1);
        hi[i] = packh2(h0, h1);
        lo[i] = packh2(__float2half_rn((w0 - __half2float(h0)) * 4096.f),
                       __float2half_rn((w1 - __half2float(h1)) * 4096.f));
    }
}

// ---------------------------------------------------------------------------
// init
// ---------------------------------------------------------------------------
__global__ void init_state_k(const float* __restrict__ memory) {
    int i0 = blockIdx.x * blockDim.x + threadIdx.x;
    int stride = gridDim.x * blockDim.x;
    if (i0 < MAX_ITERS) g_loss[i0] = 0.0;
    for (int i = i0; i < BATCH * N0 / 4; i += stride) {
        float4 m4 = *(const float4*)&memory[(i * 4) & (N0 - 1)];
        ((float4*)g_v0)[i] = m4;
        float4 t4 = make_float4(tanhf(m4.x), tanhf(m4.y), tanhf(m4.z), tanhf(m4.w));
        ((float4*)g_t0)[i] = t4;
        uint2 hi, lo;
        split4(t4, hi, lo);
        g_t0ph[i] = hi;
        g_t0pl[i] = lo;
        ((float4*)g_e0)[i] = make_float4(0.f, 0.f, 0.f, 0.f);
    }
    for (int i = i0; i < BATCH * N1 / 4; i += stride) {
        ((float4*)g_e1)[i] = make_float4(0.f, 0.f, 0.f, 0.f);
        g_e1ph[i] = make_uint2(0, 0);
        g_e1pl[i] = make_uint2(0, 0);
    }
}

// ---------------------------------------------------------------------------
// Split-K GEMM (pure partial writer), fp16-split emulation (~fp32 accurate).
// D = [Ah.Bh] + 2^-12 [Ah.Bl' + Al'.Bh], two fp32 accumulators.
// CTA 64m x 64n, 4 warps (2m x 2n, each 32x32 -> 64 accum regs). KC=16,
// 4-stage cp.async, cp_wait<2>, KPART=1024, 4 CTAs/SM (16 warps/SM).
// Modes: 0: t0@W0^T -> sQ1[p] (2p)   1: t1@W1^T -> sQ2[p] (4p)
//        2: e1@W0   -> sP0[p] (4p)   3: e2@W1   -> sP1[p] (8p)
// ---------------------------------------------------------------------------
constexpr int KC = 16, KP = 8, KPART = 1024;
constexpr int BMT = 64;      // CTA m-tile
constexpr int LDA2 = 12;     // A smem stride in u32 words (rows = m)
constexpr int LDBT2 = 12;    // B smem stride, BT (rows = n)
constexpr int LDBN2 = 72;    // B smem stride, NN (rows = kpair); 72%32=8
constexpr int TILEW_A = BMT * LDA2;   // 768 words per A component
constexpr int TILEW_B = 768;          // words per B component (64*12 = 8*72+pad)
constexpr int STAGE_W = 2 * TILEW_A + 2 * TILEW_B;  // 3072 words (12 KB)
constexpr int STG = 4;
constexpr int SMEM_BYTES = STG * STAGE_W * 4;       // 49152 B -> 4 CTAs/SM

template <int MODE>
__device__ __forceinline__ void gemm_body(int bx, int by, int part) {
    constexpr bool BT = (MODE == 0 || MODE == 1);
    constexpr int NF = (MODE == 0) ? N1 : (MODE == 1) ? N2 : (MODE == 2) ? N0 : N1;
    constexpr int KF = (MODE == 0) ? N0 : (MODE == 1) ? N1 : (MODE == 2) ? N1 : N2;
    constexpr int KPF = KF / 2;      // pairs per A row
    constexpr int NCH = KPART / KC;  // 64

    const uint32_t* __restrict__ Aph = (const uint32_t*)(
        (MODE == 0) ? g_t0ph : (MODE == 1) ? g_t1ph : (MODE == 2) ? g_e1ph : g_e2ph);
    const uint32_t* __restrict__ Apl = (const uint32_t*)(
        (MODE == 0) ? g_t0pl : (MODE == 1) ? g_t1pl : (MODE == 2) ? g_e1pl : g_e2pl);
    const uint32_t* __restrict__ Bph =
        (MODE == 0) ? g_W0bth : (MODE == 1) ? g_W1bth : (MODE == 2) ? g_W0nnh : g_W1nnh;
    const uint32_t* __restrict__ Bpl =
        (MODE == 0) ? g_W0btl : (MODE == 1) ? g_W1btl : (MODE == 2) ? g_W0nnl : g_W1nnl;
    float* __restrict__ dst =
        (MODE == 0) ? sQ1[part] : (MODE == 1) ? sQ2[part]
        : (MODE == 2) ? sP0[part] : sP1[part];

    extern __shared__ uint32_t smw[];
    const uint32_t sb = s2u(smw);
    const int tid = threadIdx.x;
    const int wid = tid >> 5;
    const int lane = tid & 31;
    const int tq = lane >> 2;   // 0..7
    const int tr = lane & 3;    // 0..3
    const int wm = wid >> 1;    // 0..1 (m-warp)
    const int wn = wid & 1;     // 0..1 (n-warp)
    const int bm = by * BMT;
    const int bn = bx * 64;

    auto load_chunk = [&](int c, int st) {
        const int ktp = part * (KPART / 2) + c * KP;  // pair offset
        uint32_t base = sb + (uint32_t)st * STAGE_W * 4;
        // A: 64 rows x 8 pairs, hi+lo -> 128 16B-chunks per component, 1/thread
        {
            int row = tid >> 1, cs = (tid & 1) * 4;
            size_t go = (size_t)(bm + row) * KPF + ktp + cs;
            uint32_t so = (row * LDA2 + cs) * 4;
            cp_async16(base + so, Aph + go);
            cp_async16(base + TILEW_A * 4 + so, Apl + go);
        }
        uint32_t bbase = base + 2 * TILEW_A * 4;
        if (BT) {
            // B: 64 n-rows x 8 pairs -> 128 16B-chunks per component, 1/thread
            int row = tid >> 1, cs = (tid & 1) * 4;
            size_t go = (size_t)(bn + row) * KPF + ktp + cs;
            uint32_t so = (row * LDBT2 + cs) * 4;
            cp_async16(bbase + so, Bph + go);
            cp_async16(bbase + TILEW_B * 4 + so, Bpl + go);
        } else {
            // B: 8 kpair-rows x 64 n -> 128 16B-chunks per component, 1/thread
            int row = tid >> 4, cs = (tid & 15) * 4;
            size_t go = (size_t)(ktp + row) * NF + bn + cs;
            uint32_t so = (row * LDBN2 + cs) * 4;
            cp_async16(bbase + so, Bph + go);
            cp_async16(bbase + TILEW_B * 4 + so, Bpl + go);
        }
        cp_commit();
    };

    float d0[2][4][4], d1[2][4][4];
#pragma unroll
    for (int mi = 0; mi < 2; mi++)
#pragma unroll
        for (int ni = 0; ni < 4; ni++)
#pragma unroll
            for (int r = 0; r < 4; r++) { d0[mi][ni][r] = 0.0f; d1[mi][ni][r] = 0.0f; }

    // prologue: 3 chunks in flight
    load_chunk(0, 0);
    load_chunk(1, 1);
    load_chunk(2, 2);

    for (int c = 0; c < NCH; c++) {
        cp_wait<2>();      // oldest outstanding group (chunk c) complete
        __syncthreads();   // all warps past compute of c-1 before reloading its stage
        int nc = c + 3;
        if (nc < NCH) load_chunk(nc, nc & 3);
        else cp_commit();  // keep group accounting aligned through the tail

        const uint32_t* Ah = smw + (c & 3) * STAGE_W;
        const uint32_t* Al = Ah + TILEW_A;
        const uint32_t* Bh = Ah + 2 * TILEW_A;
        const uint32_t* Bl = Bh + TILEW_B;

        uint32_t ah[2][4], al[2][4];
#pragma unroll
        for (int mi = 0; mi < 2; mi++) {
            int r = wm * 32 + mi * 16 + tq;
            ah[mi][0] = Ah[r * LDA2 + tr];
            ah[mi][1] = Ah[(r + 8) * LDA2 + tr];
            ah[mi][2] = Ah[r * LDA2 + tr + 4];
            ah[mi][3] = Ah[(r + 8) * LDA2 + tr + 4];
            al[mi][0] = Al[r * LDA2 + tr];
            al[mi][1] = Al[(r + 8) * LDA2 + tr];
            al[mi][2] = Al[r * LDA2 + tr + 4];
            al[mi][3] = Al[(r + 8) * LDA2 + tr + 4];
        }
        uint32_t bh[4][2], bl[4][2];
#pragma unroll
        for (int ni = 0; ni < 4; ni++) {
            int n = wn * 32 + ni * 8 + tq;
            if (BT) {
                bh[ni][0] = Bh[n * LDBT2 + tr];
                bh[ni][1] = Bh[n * LDBT2 + tr + 4];
                bl[ni][0] = Bl[n * LDBT2 + tr];
                bl[ni][1] = Bl[n * LDBT2 + tr + 4];
            } else {
                bh[ni][0] = Bh[tr * LDBN2 + n];
                bh[ni][1] = Bh[(tr + 4) * LDBN2 + n];
                bl[ni][0] = Bl[tr * LDBN2 + n];
                bl[ni][1] = Bl[(tr + 4) * LDBN2 + n];
            }
        }
#pragma unroll
        for (int mi = 0; mi < 2; mi++)
#pragma unroll
            for (int ni = 0; ni < 4; ni++) {
                mma16(d0[mi][ni], ah[mi], bh[ni]);   // hh
                mma16(d1[mi][ni], ah[mi], bl[ni]);   // h * lo'
                mma16(d1[mi][ni], al[mi], bh[ni]);   // lo' * h
            }
    }

    // write partial tile: D = d0 + d1 * 2^-12
#pragma unroll
    for (int mi = 0; mi < 2; mi++)
#pragma unroll
        for (int ni = 0; ni < 4; ni++)
#pragma unroll
            for (int hf = 0; hf < 2; hf++) {
                int row = bm + wm * 32 + mi * 16 + tq + hf * 8;
                int col = bn + wn * 32 + ni * 8 + tr * 2;
                float px = d0[mi][ni][hf * 2] + d1[mi][ni][hf * 2] * INV4096;
                float py = d0[mi][ni][hf * 2 + 1] + d1[mi][ni][hf * 2 + 1] * INV4096;
                *(float2*)&dst[(size_t)row * NF + col] = make_float2(px, py);
            }
}

// ---------------------------------------------------------------------------
// Fused phase GEMM kernels (1-D grid of uniform-duration CTAs)
// m-tiles per GEMM = 4 (BATCH/64).
// upd: mode2 (4p x 32n x 4m = 512) + mode3 (8 x 64 x 4 = 2048) = 2560
// err: mode0 (2p x 64n x 4m = 512) + mode1 (4 x 128 x 4 = 2048) = 2560
// ---------------------------------------------------------------------------
__global__ __launch_bounds__(128, 4)
void upd_gemm() {
    int b = blockIdx.x;
    if (b < 512) {
        int part = b >> 7, t = b & 127;
        gemm_body<2>(t & 31, t >> 5, part);
    } else {
        int b2 = b - 512;
        int part = b2 >> 8, t = b2 & 255;
        gemm_body<3>(t & 63, t >> 6, part);
    }
}
__global__ __launch_bounds__(128, 4)
void err_gemm(int boff) {
    int b = blockIdx.x + boff;
    if (b < 512) {
        int part = b >> 8, t = b & 255;
        gemm_body<0>(t & 63, t >> 6, part);
    } else {
        int b2 = b - 512;
        int part = b2 >> 9, t = b2 & 511;
        gemm_body<1>(t & 127, t >> 7, part);
    }
}

// ---------------------------------------------------------------------------
// Epilogue kernels (elementwise, float4; also emit packed fp16 splits)
// ---------------------------------------------------------------------------
__device__ __forceinline__ void block_loss(float lsum, int loss_idx) {
    __shared__ float wred[8];
    int tid = threadIdx.x;
#pragma unroll
    for (int o = 16; o > 0; o >>= 1)
        lsum += __shfl_down_sync(0xffffffffu, lsum, o);
    if ((tid & 31) == 0) wred[tid >> 5] = lsum;
    __syncthreads();
    if (tid == 0 && loss_idx >= 0) {
        float s = 0.f;
#pragma unroll
        for (int w = 0; w < 8; w++) s += wred[w];
        atomicAdd(&g_loss[loss_idx], (double)s);
    }
}

// grid 1536 x 256 : v0 update (131072 f4) then v1 update (262144 f4)
__global__ __launch_bounds__(256)
void upd_epi(const float* __restrict__ memory, const float* __restrict__ lr_p,
             int loss_idx) {
    int i = blockIdx.x * blockDim.x + threadIdx.x;
    float lr = *lr_p;
    float lsum = 0.f;
    if (i < BATCH * N0 / 4) {
        float4 acc[4];
#pragma unroll
        for (int p = 0; p < 4; p++) acc[p] = ((const float4*)sP0[p])[i];
        float4 v4 = ((const float4*)g_v0)[i];
        float4 e4 = ((const float4*)g_e0)[i];
        float4 t4 = ((const float4*)g_t0)[i];
        float4 m4 = *(const float4*)&memory[(i * 4) & (N0 - 1)];
        float* v = &v4.x; float* e = &e4.x; float* t = &t4.x; float* m = &m4.x;
        float4 nv4, nt4, ne4;
        float* nv = &nv4.x; float* nt = &nt4.x; float* ne = &ne4.x;
#pragma unroll
        for (int c = 0; c < 4; c++) {
            float g = ((&acc[0].x)[c] + (&acc[1].x)[c]) +
                      ((&acc[2].x)[c] + (&acc[3].x)[c]);
            float sg = (v[c] > 0.f) ? 1.f : ((v[c] < 0.f) ? -1.f : 0.f);
            float x = fmaxf(v[c] + lr * (-e[c] - LAMB * sg + (1.f - t[c] * t[c]) * g), 0.f);
            nv[c] = x;
            nt[c] = tanhf(x);
            float er = x - m[c];
            ne[c] = er;
            lsum += er * er;
        }
        ((float4*)g_v0)[i] = nv4;
        ((float4*)g_t0)[i] = nt4;
        ((float4*)g_e0)[i] = ne4;
        uint2 hi, lo;
        split4(nt4, hi, lo);
        g_t0ph[i] = hi;
        g_t0pl[i] = lo;
    } else {
        int j = i - BATCH * N0 / 4;
        float4 acc[8];
#pragma unroll
        for (int p = 0; p < 8; p++) acc[p] = ((const float4*)sP1[p])[j];
        float4 v4 = ((const float4*)g_v1)[j];
        float4 e4 = ((const float4*)g_e1)[j];
        float4 t4 = ((const float4*)g_t1)[j];
        float* v = &v4.x; float* e = &e4.x; float* t = &t4.x;
        float4 nv4, nt4;
        float* nv = &nv4.x; float* nt = &nt4.x;
#pragma unroll
        for (int c = 0; c < 4; c++) {
            float g = (((&acc[0].x)[c] + (&acc[1].x)[c]) +
                       ((&acc[2].x)[c] + (&acc[3].x)[c])) +
                      (((&acc[4].x)[c] + (&acc[5].x)[c]) +
                       ((&acc[6].x)[c] + (&acc[7].x)[c]));
            float x = fmaxf(v[c] + lr * (-e[c] + (1.f - t[c] * t[c]) * g), 0.f);
            nv[c] = x;
            nt[c] = tanhf(x);
        }
        ((float4*)g_v1)[j] = nv4;
        ((float4*)g_t1)[j] = nt4;
        uint2 hi, lo;
        split4(nt4, hi, lo);
        g_t1ph[j] = hi;
        g_t1pl[j] = lo;
    }
    block_loss(lsum, loss_idx);
}

// grid 3072 x 256 : e1 (262144 f4, skipped when mode=1) then e2 (524288 f4)
__global__ __launch_bounds__(256)
void err_epi(const float* __restrict__ inp, int loss_idx, int mode) {
    int i = blockIdx.x * blockDim.x + threadIdx.x;
    float lsum = 0.f;
    if (i < BATCH * N1 / 4) {
        if (mode == 0) {
            float4 q0 = ((const float4*)sQ1[0])[i];
            float4 q1 = ((const float4*)sQ1[1])[i];
            float4 v = ((const float4*)g_v1)[i];
            float4 e = make_float4(v.x - (q0.x + q1.x), v.y - (q0.y + q1.y),
                                   v.z - (q0.z + q1.z), v.w - (q0.w + q1.w));
            ((float4*)g_e1)[i] = e;
            uint2 hi, lo;
            split4(e, hi, lo);
            g_e1ph[i] = hi;
            g_e1pl[i] = lo;
            lsum = e.x * e.x + e.y * e.y + e.z * e.z + e.w * e.w;
        }
    } else {
        int j = i - BATCH * N1 / 4;
        float4 q0 = ((const float4*)sQ2[0])[j];
        float4 q1 = ((const float4*)sQ2[1])[j];
        float4 q2 = ((const float4*)sQ2[2])[j];
        float4 q3 = ((const float4*)sQ2[3])[j];
        float4 x = ((const float4*)inp)[j];
        float4 e = make_float4(x.x - ((q0.x + q1.x) + (q2.x + q3.x)),
                               x.y - ((q0.y + q1.y) + (q2.y + q3.y)),
                               x.z - ((q0.z + q1.z) + (q2.z + q3.z)),
                               x.w - ((q0.w + q1.w) + (q2.w + q3.w)));
        uint2 hi, lo;
        split4(e, hi, lo);
        g_e2ph[j] = hi;
        g_e2pl[j] = lo;
        lsum = e.x * e.x + e.y * e.y + e.z * e.z + e.w * e.w;
    }
    block_loss(lsum, loss_idx);
}

// grid 1024 x 256 : v1 = sum(sQ1), t1 = tanh(v1) (+ t1 splits)
__global__ __launch_bounds__(256)
void fwd_epi() {
    int i = blockIdx.x * blockDim.x + threadIdx.x;
    float4 q0 = ((const float4*)sQ1[0])[i];
    float4 q1 = ((const float4*)sQ1[1])[i];
    float4 q = make_float4(q0.x + q1.x, q0.y + q1.y, q0.z + q1.z, q0.w + q1.w);
    ((float4*)g_v1)[i] = q;
    float4 t = make_float4(tanhf(q.x), tanhf(q.y), tanhf(q.z), tanhf(q.w));
    ((float4*)g_t1)[i] = t;
    uint2 hi, lo;
    split4(t, hi, lo);
    g_t1ph[i] = hi;
    g_t1pl[i] = lo;
}

__global__ void finalize_kernel(float* __restrict__ out, int n) {
    int i = threadIdx.x;
    if (i < n) out[i] = (float)(g_loss[i] * (100.0 / (double)BATCH));
}

// ---------------------------------------------------------------------------
// Launch (graph-capturable)
// Inputs: batch_inp, W0, W1, memory, n_iters, inf_lr
// ---------------------------------------------------------------------------
extern "C" void kernel_launch(void* const* d_in, const int* in_sizes, int n_in,
                              void* d_out, int out_size) {
    const float* batch_inp = (const float*)d_in[0];
    const float* W0 = (const float*)d_in[1];
    const float* W1 = (const float*)d_in[2];
    const float* memory = (const float*)d_in[3];
    const float* inf_lr = (const float*)d_in[5];

    int n_iters = out_size;
    if (n_iters > MAX_ITERS) n_iters = MAX_ITERS;

    cudaFuncSetAttribute(upd_gemm, cudaFuncAttributeMaxDynamicSharedMemorySize, SMEM_BYTES);
    cudaFuncSetAttribute(err_gemm, cudaFuncAttributeMaxDynamicSharedMemorySize, SMEM_BYTES);

    // weight splits (pure function of inputs; recomputed each call)
    split_w_bt<<<2048, 256>>>(W0, 0, N1 * N0 / 2);
    split_w_bt<<<4096, 256>>>(W1, 1, N2 * N1 / 2);
    split_w_nn<<<2048, 256>>>(W0, 0);
    split_w_nn<<<4096, 256>>>(W1, 1);
    init_state_k<<<512, 256>>>(memory);

    // init: v1 = t0@W0^T, t1 = tanh(v1); e1 stays exactly 0; e2 = inp - t1@W1^T
    err_gemm<<<512, 128, SMEM_BYTES>>>(0);      // mode 0 -> sQ1[0..1]
    fwd_epi<<<1024, 256>>>();
    err_gemm<<<2048, 128, SMEM_BYTES>>>(512);   // mode 1 -> sQ2[0..3]
    err_epi<<<3072, 256>>>(batch_inp, -1, 1);   // e2 only, no loss

    for (int it = 0; it < n_iters; it++) {
        upd_gemm<<<2560, 128, SMEM_BYTES>>>();
        upd_epi<<<1536, 256>>>(memory, inf_lr, it);
        err_gemm<<<2560, 128, SMEM_BYTES>>>(0);
        err_epi<<<3072, 256>>>(batch_inp, it, 0);
    }

    finalize_kernel<<<1, MAX_ITERS>>>((float*)d_out, n_iters);
}

// round 17
// speedup vs baseline: 1.4297x; 1.2723x over previous
#include <cuda_runtime.h>
#include <cuda_fp16.h>
#include <math.h>
#include <stdint.h>

// ---------------------------------------------------------------------------
// Problem constants
// ---------------------------------------------------------------------------
constexpr int BATCH = 256;
constexpr int N0 = 2048;
constexpr int N1 = 4096;
constexpr int N2 = 8192;
constexpr float LAMB = 0.5f;
constexpr int MAX_ITERS = 64;
constexpr float INV4096 = 1.0f / 4096.0f;

// ---------------------------------------------------------------------------
// Persistent state + scratch (__device__ globals).
// RULE (learned R3/R4/R9): device globals may ONLY be referenced from device
// code — never passed as kernel arguments from host.
// ---------------------------------------------------------------------------
__device__ float g_v0[BATCH * N0], g_t0[BATCH * N0], g_e0[BATCH * N0];
__device__ float g_v1[BATCH * N1], g_t1[BATCH * N1], g_e1[BATCH * N1];
__device__ float sP0[4][BATCH * N0];   // e1@W0 partials (UPD0, 4 K-parts)
__device__ float sP1[8][BATCH * N1];   // e2@W1 partials (UPD1, 8 K-parts)
__device__ float sQ1[2][BATCH * N1];   // t0@W0^T partials (2 parts)
__device__ float sQ2[4][BATCH * N2];   // t1@W1^T partials (4 parts)
// fp16-split packed activations (hi, lo*4096), 2 fp16 per u32, pairs along k
__device__ uint2 g_t0ph[BATCH * N0 / 4], g_t0pl[BATCH * N0 / 4];
__device__ uint2 g_t1ph[BATCH * N1 / 4], g_t1pl[BATCH * N1 / 4];
__device__ uint2 g_e1ph[BATCH * N1 / 4];   // hi only (updates are 1-term)
__device__ uint2 g_e2ph[BATCH * N2 / 4];   // hi only
// fp16-split packed weights. bt (BT modes, hi+lo); nn (update modes, hi only)
__device__ uint32_t g_W0bth[(size_t)N1 * N0 / 2], g_W0btl[(size_t)N1 * N0 / 2];
__device__ uint32_t g_W0nnh[(size_t)N1 * N0 / 2];
__device__ uint32_t g_W1bth[(size_t)N2 * N1 / 2], g_W1btl[(size_t)N2 * N1 / 2];
__device__ uint32_t g_W1nnh[(size_t)N2 * N1 / 2];
__device__ double g_loss[MAX_ITERS];

// ---------------------------------------------------------------------------
// PTX helpers (sm_80 baseline; ptxas target is plain sm_103)
// ---------------------------------------------------------------------------
__device__ __forceinline__ uint32_t s2u(const void* p) {
    uint32_t a;
    asm("{ .reg .u64 t; cvta.to.shared.u64 t, %1; cvt.u32.u64 %0, t; }"
        : "=r"(a) : "l"(p));
    return a;
}
__device__ __forceinline__ void cp_async16(uint32_t saddr, const void* gaddr) {
    asm volatile("cp.async.cg.shared.global [%0], [%1], 16;"
                 :: "r"(saddr), "l"(gaddr) : "memory");
}
__device__ __forceinline__ void cp_commit() {
    asm volatile("cp.async.commit_group;" ::: "memory");
}
template <int N>
__device__ __forceinline__ void cp_wait() {
    asm volatile("cp.async.wait_group %0;" :: "n"(N) : "memory");
}
__device__ __forceinline__ void mma16(float* d, const uint32_t* a, const uint32_t* b) {
    asm volatile(
        "mma.sync.aligned.m16n8k16.row.col.f32.f16.f16.f32 "
        "{%0,%1,%2,%3}, {%4,%5,%6,%7}, {%8,%9}, {%0,%1,%2,%3};"
        : "+f"(d[0]), "+f"(d[1]), "+f"(d[2]), "+f"(d[3])
        : "r"(a[0]), "r"(a[1]), "r"(a[2]), "r"(a[3]), "r"(b[0]), "r"(b[1]));
}

__device__ __forceinline__ uint32_t packh2(__half a, __half b) {
    return (uint32_t)__half_as_ushort(a) | ((uint32_t)__half_as_ushort(b) << 16);
}
__device__ __forceinline__ void split4(float4 x, uint2& hi, uint2& lo) {
    __half h0 = __float2half_rn(x.x), h1 = __float2half_rn(x.y);
    __half h2 = __float2half_rn(x.z), h3 = __float2half_rn(x.w);
    hi.x = packh2(h0, h1);
    hi.y = packh2(h2, h3);
    float l0 = (x.x - __half2float(h0)) * 4096.f;
    float l1 = (x.y - __half2float(h1)) * 4096.f;
    float l2 = (x.z - __half2float(h2)) * 4096.f;
    float l3 = (x.w - __half2float(h3)) * 4096.f;
    lo.x = packh2(__float2half_rn(l0), __float2half_rn(l1));
    lo.y = packh2(__float2half_rn(l2), __float2half_rn(l3));
}
__device__ __forceinline__ uint2 pack4hi(float4 x) {
    uint2 hi;
    hi.x = packh2(__float2half_rn(x.x), __float2half_rn(x.y));
    hi.y = packh2(__float2half_rn(x.z), __float2half_rn(x.w));
    return hi;
}

// ---------------------------------------------------------------------------
// prep: weight splits (device-side symbol selection per RULE)
// ---------------------------------------------------------------------------
__global__ void split_w_bt(const float* __restrict__ W, int which, int npairs) {
    uint32_t* __restrict__ hi = which ? g_W1bth : g_W0bth;
    uint32_t* __restrict__ lo = which ? g_W1btl : g_W0btl;
    int i0 = blockIdx.x * blockDim.x + threadIdx.x;
    int stride = gridDim.x * blockDim.x;
    for (int i = i0; i < npairs; i += stride) {
        float w0 = W[2 * i], w1 = W[2 * i + 1];
        __half h0 = __float2half_rn(w0), h1 = __float2half_rn(w1);
        hi[i] = packh2(h0, h1);
        lo[i] = packh2(__float2half_rn((w0 - __half2float(h0)) * 4096.f),
                       __float2half_rn((w1 - __half2float(h1)) * 4096.f));
    }
}
// NN layout [kpair][n], hi only (updates are 1-term)
__global__ void split_w_nn(const float* __restrict__ W, int which) {
    uint32_t* __restrict__ hi = which ? g_W1nnh : g_W0nnh;
    const int N = which ? N1 : N0;
    const int npairs_total = which ? (N2 / 2) * N1 : (N1 / 2) * N0;
    int i0 = blockIdx.x * blockDim.x + threadIdx.x;
    int stride = gridDim.x * blockDim.x;
    for (int i = i0; i < npairs_total; i += stride) {
        int kp = i / N, n = i - kp * N;
        float w0 = W[(size_t)(2 * kp) * N + n];
        float w1 = W[(size_t)(2 * kp + 1) * N + n];
        hi[i] = packh2(__float2half_rn(w0), __float2half_rn(w1));
    }
}

// ---------------------------------------------------------------------------
// init
// ---------------------------------------------------------------------------
__global__ void init_state_k(const float* __restrict__ memory) {
    int i0 = blockIdx.x * blockDim.x + threadIdx.x;
    int stride = gridDim.x * blockDim.x;
    if (i0 < MAX_ITERS) g_loss[i0] = 0.0;
    for (int i = i0; i < BATCH * N0 / 4; i += stride) {
        float4 m4 = *(const float4*)&memory[(i * 4) & (N0 - 1)];
        ((float4*)g_v0)[i] = m4;
        float4 t4 = make_float4(tanhf(m4.x), tanhf(m4.y), tanhf(m4.z), tanhf(m4.w));
        ((float4*)g_t0)[i] = t4;
        uint2 hi, lo;
        split4(t4, hi, lo);
        g_t0ph[i] = hi;
        g_t0pl[i] = lo;
        ((float4*)g_e0)[i] = make_float4(0.f, 0.f, 0.f, 0.f);
    }
    for (int i = i0; i < BATCH * N1 / 4; i += stride) {
        ((float4*)g_e1)[i] = make_float4(0.f, 0.f, 0.f, 0.f);
        g_e1ph[i] = make_uint2(0, 0);
    }
}

// ---------------------------------------------------------------------------
// Split-K GEMM (pure partial writer).
// Modes 0,1 (BT, prediction path): 3-term fp16-split, ~fp32 accurate:
//   D = [Ah.Bh] + 2^-12 [Ah.Bl' + Al'.Bh]
// Modes 2,3 (NN, update gradient path): 1-term hh (rel err ~1e-3 on g,
//   damped by lr=0.05 before entering state).
// CTA 64m x 64n, 4 warps (2m x 2n, warp tile 32x32). KC=16, 4-stage
// cp.async, cp_wait<2>, KPART=1024, 4 CTAs/SM (16 warps/SM).
// ---------------------------------------------------------------------------
constexpr int KC = 16, KP = 8, KPART = 1024;
constexpr int BMT = 64;      // CTA m-tile
constexpr int LDA2 = 12;     // A smem stride in u32 words (rows = m)
constexpr int LDBT2 = 12;    // B smem stride, BT (rows = n)
constexpr int LDBN2 = 72;    // B smem stride, NN (rows = kpair); 72%32=8
constexpr int TILEW_A = BMT * LDA2;   // 768 words per A component
constexpr int TILEW_B = 768;          // words per B component
constexpr int STAGE_W = 2 * TILEW_A + 2 * TILEW_B;  // 3072 words (12 KB)
constexpr int STG = 4;
constexpr int SMEM_BYTES = STG * STAGE_W * 4;       // 49152 B -> 4 CTAs/SM

template <int MODE>
__device__ __forceinline__ void gemm_body(int bx, int by, int part) {
    constexpr bool BT = (MODE == 0 || MODE == 1);
    constexpr int TERMS = BT ? 3 : 1;
    constexpr int NF = (MODE == 0) ? N1 : (MODE == 1) ? N2 : (MODE == 2) ? N0 : N1;
    constexpr int KF = (MODE == 0) ? N0 : (MODE == 1) ? N1 : (MODE == 2) ? N1 : N2;
    constexpr int KPF = KF / 2;      // pairs per A row
    constexpr int NCH = KPART / KC;  // 64

    const uint32_t* __restrict__ Aph = (const uint32_t*)(
        (MODE == 0) ? g_t0ph : (MODE == 1) ? g_t1ph : (MODE == 2) ? g_e1ph : g_e2ph);
    const uint32_t* __restrict__ Apl = (const uint32_t*)(
        (MODE == 0) ? g_t0pl : (MODE == 1) ? g_t1pl : (const uint2*)nullptr);
    const uint32_t* __restrict__ Bph =
        (MODE == 0) ? g_W0bth : (MODE == 1) ? g_W1bth : (MODE == 2) ? g_W0nnh : g_W1nnh;
    const uint32_t* __restrict__ Bpl =
        (MODE == 0) ? g_W0btl : (MODE == 1) ? g_W1btl : (uint32_t*)nullptr;
    float* __restrict__ dst =
        (MODE == 0) ? sQ1[part] : (MODE == 1) ? sQ2[part]
        : (MODE == 2) ? sP0[part] : sP1[part];

    extern __shared__ uint32_t smw[];
    const uint32_t sb = s2u(smw);
    const int tid = threadIdx.x;
    const int wid = tid >> 5;
    const int lane = tid & 31;
    const int tq = lane >> 2;   // 0..7
    const int tr = lane & 3;    // 0..3
    const int wm = wid >> 1;    // 0..1 (m-warp)
    const int wn = wid & 1;     // 0..1 (n-warp)
    const int bm = by * BMT;
    const int bn = bx * 64;

    auto load_chunk = [&](int c, int st) {
        const int ktp = part * (KPART / 2) + c * KP;  // pair offset
        uint32_t base = sb + (uint32_t)st * STAGE_W * 4;
        // A: 64 rows x 8 pairs -> 128 16B-chunks per component, 1/thread
        {
            int row = tid >> 1, cs = (tid & 1) * 4;
            size_t go = (size_t)(bm + row) * KPF + ktp + cs;
            uint32_t so = (row * LDA2 + cs) * 4;
            cp_async16(base + so, Aph + go);
            if (TERMS == 3) cp_async16(base + TILEW_A * 4 + so, Apl + go);
        }
        uint32_t bbase = base + 2 * TILEW_A * 4;
        if (BT) {
            int row = tid >> 1, cs = (tid & 1) * 4;
            size_t go = (size_t)(bn + row) * KPF + ktp + cs;
            uint32_t so = (row * LDBT2 + cs) * 4;
            cp_async16(bbase + so, Bph + go);
            cp_async16(bbase + TILEW_B * 4 + so, Bpl + go);
        } else {
            int row = tid >> 4, cs = (tid & 15) * 4;
            size_t go = (size_t)(ktp + row) * NF + bn + cs;
            uint32_t so = (row * LDBN2 + cs) * 4;
            cp_async16(bbase + so, Bph + go);
        }
        cp_commit();
    };

    float d0[2][4][4], d1[2][4][4];
#pragma unroll
    for (int mi = 0; mi < 2; mi++)
#pragma unroll
        for (int ni = 0; ni < 4; ni++)
#pragma unroll
            for (int r = 0; r < 4; r++) { d0[mi][ni][r] = 0.0f; d1[mi][ni][r] = 0.0f; }

    // prologue: 3 chunks in flight
    load_chunk(0, 0);
    load_chunk(1, 1);
    load_chunk(2, 2);

    for (int c = 0; c < NCH; c++) {
        cp_wait<2>();      // oldest outstanding group (chunk c) complete
        __syncthreads();   // all warps past compute of c-1 before reloading its stage
        int nc = c + 3;
        if (nc < NCH) load_chunk(nc, nc & 3);
        else cp_commit();  // keep group accounting aligned through the tail

        const uint32_t* Ah = smw + (c & 3) * STAGE_W;
        const uint32_t* Al = Ah + TILEW_A;
        const uint32_t* Bh = Ah + 2 * TILEW_A;
        const uint32_t* Bl = Bh + TILEW_B;

        uint32_t ah[2][4], al[2][4];
#pragma unroll
        for (int mi = 0; mi < 2; mi++) {
            int r = wm * 32 + mi * 16 + tq;
            ah[mi][0] = Ah[r * LDA2 + tr];
            ah[mi][1] = Ah[(r + 8) * LDA2 + tr];
            ah[mi][2] = Ah[r * LDA2 + tr + 4];
            ah[mi][3] = Ah[(r + 8) * LDA2 + tr + 4];
            if (TERMS == 3) {
                al[mi][0] = Al[r * LDA2 + tr];
                al[mi][1] = Al[(r + 8) * LDA2 + tr];
                al[mi][2] = Al[r * LDA2 + tr + 4];
                al[mi][3] = Al[(r + 8) * LDA2 + tr + 4];
            }
        }
        uint32_t bh[4][2], bl[4][2];
#pragma unroll
        for (int ni = 0; ni < 4; ni++) {
            int n = wn * 32 + ni * 8 + tq;
            if (BT) {
                bh[ni][0] = Bh[n * LDBT2 + tr];
                bh[ni][1] = Bh[n * LDBT2 + tr + 4];
                bl[ni][0] = Bl[n * LDBT2 + tr];
                bl[ni][1] = Bl[n * LDBT2 + tr + 4];
            } else {
                bh[ni][0] = Bh[tr * LDBN2 + n];
                bh[ni][1] = Bh[(tr + 4) * LDBN2 + n];
            }
        }
#pragma unroll
        for (int mi = 0; mi < 2; mi++)
#pragma unroll
            for (int ni = 0; ni < 4; ni++) {
                mma16(d0[mi][ni], ah[mi], bh[ni]);       // hh
                if (TERMS == 3) {
                    mma16(d1[mi][ni], ah[mi], bl[ni]);   // h * lo'
                    mma16(d1[mi][ni], al[mi], bh[ni]);   // lo' * h
                }
            }
    }

    // write partial tile: D = d0 (+ d1 * 2^-12 for 3-term)
#pragma unroll
    for (int mi = 0; mi < 2; mi++)
#pragma unroll
        for (int ni = 0; ni < 4; ni++)
#pragma unroll
            for (int hf = 0; hf < 2; hf++) {
                int row = bm + wm * 32 + mi * 16 + tq + hf * 8;
                int col = bn + wn * 32 + ni * 8 + tr * 2;
                float px = d0[mi][ni][hf * 2];
                float py = d0[mi][ni][hf * 2 + 1];
                if (TERMS == 3) {
                    px += d1[mi][ni][hf * 2] * INV4096;
                    py += d1[mi][ni][hf * 2 + 1] * INV4096;
                }
                *(float2*)&dst[(size_t)row * NF + col] = make_float2(px, py);
            }
}

// ---------------------------------------------------------------------------
// Fused phase GEMM kernels (1-D grid of uniform-duration CTAs)
// upd: mode2 (4p x 32n x 4m = 512) + mode3 (8 x 64 x 4 = 2048) = 2560
// err: mode0 (2p x 64n x 4m = 512) + mode1 (4 x 128 x 4 = 2048) = 2560
// ---------------------------------------------------------------------------
__global__ __launch_bounds__(128, 4)
void upd_gemm() {
    int b = blockIdx.x;
    if (b < 512) {
        int part = b >> 7, t = b & 127;
        gemm_body<2>(t & 31, t >> 5, part);
    } else {
        int b2 = b - 512;
        int part = b2 >> 8, t = b2 & 255;
        gemm_body<3>(t & 63, t >> 6, part);
    }
}
__global__ __launch_bounds__(128, 4)
void err_gemm(int boff) {
    int b = blockIdx.x + boff;
    if (b < 512) {
        int part = b >> 8, t = b & 255;
        gemm_body<0>(t & 63, t >> 6, part);
    } else {
        int b2 = b - 512;
        int part = b2 >> 9, t = b2 & 511;
        gemm_body<1>(t & 127, t >> 7, part);
    }
}

// ---------------------------------------------------------------------------
// Epilogue kernels (elementwise, float4; emit fp16 packs as needed)
// ---------------------------------------------------------------------------
__device__ __forceinline__ void block_loss(float lsum, int loss_idx) {
    __shared__ float wred[8];
    int tid = threadIdx.x;
#pragma unroll
    for (int o = 16; o > 0; o >>= 1)
        lsum += __shfl_down_sync(0xffffffffu, lsum, o);
    if ((tid & 31) == 0) wred[tid >> 5] = lsum;
    __syncthreads();
    if (tid == 0 && loss_idx >= 0) {
        float s = 0.f;
#pragma unroll
        for (int w = 0; w < 8; w++) s += wred[w];
        atomicAdd(&g_loss[loss_idx], (double)s);
    }
}

// grid 1536 x 256 : v0 update (131072 f4) then v1 update (262144 f4)
__global__ __launch_bounds__(256)
void upd_epi(const float* __restrict__ memory, const float* __restrict__ lr_p,
             int loss_idx) {
    int i = blockIdx.x * blockDim.x + threadIdx.x;
    float lr = *lr_p;
    float lsum = 0.f;
    if (i < BATCH * N0 / 4) {
        float4 acc[4];
#pragma unroll
        for (int p = 0; p < 4; p++) acc[p] = ((const float4*)sP0[p])[i];
        float4 v4 = ((const float4*)g_v0)[i];
        float4 e4 = ((const float4*)g_e0)[i];
        float4 t4 = ((const float4*)g_t0)[i];
        float4 m4 = *(const float4*)&memory[(i * 4) & (N0 - 1)];
        float* v = &v4.x; float* e = &e4.x; float* t = &t4.x; float* m = &m4.x;
        float4 nv4, nt4, ne4;
        float* nv = &nv4.x; float* nt = &nt4.x; float* ne = &ne4.x;
#pragma unroll
        for (int c = 0; c < 4; c++) {
            float g = ((&acc[0].x)[c] + (&acc[1].x)[c]) +
                      ((&acc[2].x)[c] + (&acc[3].x)[c]);
            float sg = (v[c] > 0.f) ? 1.f : ((v[c] < 0.f) ? -1.f : 0.f);
            float x = fmaxf(v[c] + lr * (-e[c] - LAMB * sg + (1.f - t[c] * t[c]) * g), 0.f);
            nv[c] = x;
            nt[c] = tanhf(x);
            float er = x - m[c];
            ne[c] = er;
            lsum += er * er;
        }
        ((float4*)g_v0)[i] = nv4;
        ((float4*)g_t0)[i] = nt4;
        ((float4*)g_e0)[i] = ne4;
        uint2 hi, lo;
        split4(nt4, hi, lo);
        g_t0ph[i] = hi;
        g_t0pl[i] = lo;
    } else {
        int j = i - BATCH * N0 / 4;
        float4 acc[8];
#pragma unroll
        for (int p = 0; p < 8; p++) acc[p] = ((const float4*)sP1[p])[j];
        float4 v4 = ((const float4*)g_v1)[j];
        float4 e4 = ((const float4*)g_e1)[j];
        float4 t4 = ((const float4*)g_t1)[j];
        float* v = &v4.x; float* e = &e4.x; float* t = &t4.x;
        float4 nv4, nt4;
        float* nv = &nv4.x; float* nt = &nt4.x;
#pragma unroll
        for (int c = 0; c < 4; c++) {
            float g = (((&acc[0].x)[c] + (&acc[1].x)[c]) +
                       ((&acc[2].x)[c] + (&acc[3].x)[c])) +
                      (((&acc[4].x)[c] + (&acc[5].x)[c]) +
                       ((&acc[6].x)[c] + (&acc[7].x)[c]));
            float x = fmaxf(v[c] + lr * (-e[c] + (1.f - t[c] * t[c]) * g), 0.f);
            nv[c] = x;
            nt[c] = tanhf(x);
        }
        ((float4*)g_v1)[j] = nv4;
        ((float4*)g_t1)[j] = nt4;
        uint2 hi, lo;
        split4(nt4, hi, lo);
        g_t1ph[j] = hi;
        g_t1pl[j] = lo;
    }
    block_loss(lsum, loss_idx);
}

// grid 3072 x 256 : e1 (262144 f4, skipped when mode=1) then e2 (524288 f4)
__global__ __launch_bounds__(256)
void err_epi(const float* __restrict__ inp, int loss_idx, int mode) {
    int i = blockIdx.x * blockDim.x + threadIdx.x;
    float lsum = 0.f;
    if (i < BATCH * N1 / 4) {
        if (mode == 0) {
            float4 q0 = ((const float4*)sQ1[0])[i];
            float4 q1 = ((const float4*)sQ1[1])[i];
            float4 v = ((const float4*)g_v1)[i];
            float4 e = make_float4(v.x - (q0.x + q1.x), v.y - (q0.y + q1.y),
                                   v.z - (q0.z + q1.z), v.w - (q0.w + q1.w));
            ((float4*)g_e1)[i] = e;
            g_e1ph[i] = pack4hi(e);
            lsum = e.x * e.x + e.y * e.y + e.z * e.z + e.w * e.w;
        }
    } else {
        int j = i - BATCH * N1 / 4;
        float4 q0 = ((const float4*)sQ2[0])[j];
        float4 q1 = ((const float4*)sQ2[1])[j];
        float4 q2 = ((const float4*)sQ2[2])[j];
        float4 q3 = ((const float4*)sQ2[3])[j];
        float4 x = ((const float4*)inp)[j];
        float4 e = make_float4(x.x - ((q0.x + q1.x) + (q2.x + q3.x)),
                               x.y - ((q0.y + q1.y) + (q2.y + q3.y)),
                               x.z - ((q0.z + q1.z) + (q2.z + q3.z)),
                               x.w - ((q0.w + q1.w) + (q2.w + q3.w)));
        g_e2ph[j] = pack4hi(e);
        lsum = e.x * e.x + e.y * e.y + e.z * e.z + e.w * e.w;
    }
    block_loss(lsum, loss_idx);
}

// grid 1024 x 256 : v1 = sum(sQ1), t1 = tanh(v1) (+ t1 splits)
__global__ __launch_bounds__(256)
void fwd_epi() {
    int i = blockIdx.x * blockDim.x + threadIdx.x;
    float4 q0 = ((const float4*)sQ1[0])[i];
    float4 q1 = ((const float4*)sQ1[1])[i];
    float4 q = make_float4(q0.x + q1.x, q0.y + q1.y, q0.z + q1.z, q0.w + q1.w);
    ((float4*)g_v1)[i] = q;
    float4 t = make_float4(tanhf(q.x), tanhf(q.y), tanhf(q.z), tanhf(q.w));
    ((float4*)g_t1)[i] = t;
    uint2 hi, lo;
    split4(t, hi, lo);
    g_t1ph[i] = hi;
    g_t1pl[i] = lo;
}

__global__ void finalize_kernel(float* __restrict__ out, int n) {
    int i = threadIdx.x;
    if (i < n) out[i] = (float)(g_loss[i] * (100.0 / (double)BATCH));
}

// ---------------------------------------------------------------------------
// Launch (graph-capturable)
// Inputs: batch_inp, W0, W1, memory, n_iters, inf_lr
// ---------------------------------------------------------------------------
extern "C" void kernel_launch(void* const* d_in, const int* in_sizes, int n_in,
                              void* d_out, int out_size) {
    const float* batch_inp = (const float*)d_in[0];
    const float* W0 = (const float*)d_in[1];
    const float* W1 = (const float*)d_in[2];
    const float* memory = (const float*)d_in[3];
    const float* inf_lr = (const float*)d_in[5];

    int n_iters = out_size;
    if (n_iters > MAX_ITERS) n_iters = MAX_ITERS;

    cudaFuncSetAttribute(upd_gemm, cudaFuncAttributeMaxDynamicSharedMemorySize, SMEM_BYTES);
    cudaFuncSetAttribute(err_gemm, cudaFuncAttributeMaxDynamicSharedMemorySize, SMEM_BYTES);

    // weight splits (pure function of inputs; recomputed each call)
    split_w_bt<<<2048, 256>>>(W0, 0, N1 * N0 / 2);
    split_w_bt<<<4096, 256>>>(W1, 1, N2 * N1 / 2);
    split_w_nn<<<2048, 256>>>(W0, 0);
    split_w_nn<<<4096, 256>>>(W1, 1);
    init_state_k<<<512, 256>>>(memory);

    // init: v1 = t0@W0^T, t1 = tanh(v1); e1 stays exactly 0; e2 = inp - t1@W1^T
    err_gemm<<<512, 128, SMEM_BYTES>>>(0);      // mode 0 -> sQ1[0..1]
    fwd_epi<<<1024, 256>>>();
    err_gemm<<<2048, 128, SMEM_BYTES>>>(512);   // mode 1 -> sQ2[0..3]
    err_epi<<<3072, 256>>>(batch_inp, -1, 1);   // e2 only, no loss

    for (int it = 0; it < n_iters; it++) {
        upd_gemm<<<2560, 128, SMEM_BYTES>>>();
        upd_epi<<<1536, 256>>>(memory, inf_lr, it);
        err_gemm<<<2560, 128, SMEM_BYTES>>>(0);
        err_epi<<<3072, 256>>>(batch_inp, it, 0);
    }

    finalize_kernel<<<1, MAX_ITERS>>>((float*)d_out, n_iters);
}